// round 4
// baseline (speedup 1.0000x reference)
#include <cuda_runtime.h>
#include <cuda_bf16.h>
#include <math.h>

#define BB 8
#define NN 4096
#define MM 4096
#define DD 128

// ---------------- scratch (device globals: no allocation allowed) ----------
__device__ float g_d0n[BB * NN * DD];   // normalized descriptors0
__device__ float g_d1n[BB * MM * DD];   // normalized descriptors1

__device__ float g_rv0[BB * NN];        // row top-2 values / indices
__device__ float g_rv1[BB * NN];
__device__ int   g_ri0[BB * NN];
__device__ int   g_ri1[BB * NN];

__device__ float g_cv0[BB * MM];        // col top-2
__device__ float g_cv1[BB * MM];
__device__ int   g_ci0[BB * MM];
__device__ int   g_ci1[BB * MM];

__device__ int   g_m0raw[BB * NN];      // pre-mutual matches
__device__ int   g_m1raw[BB * MM];

// ---------------- helpers --------------------------------------------------
__device__ __forceinline__ void push2(float v, int i,
                                      float& v0, int& i0, float& v1, int& i1) {
    if (v > v0) { v1 = v0; i1 = i0; v0 = v; i0 = i; }
    else if (v > v1) { v1 = v; i1 = i; }
}

__device__ __forceinline__ bool better(float va, int ia, float vb, int ib) {
    return (va > vb) || (va == vb && ia < ib);
}

// merge another (ov0,oi0,ov1,oi1) top-2 set into (v0,i0,v1,i1)
__device__ __forceinline__ void merge2(float& v0, int& i0, float& v1, int& i1,
                                       float ov0, int oi0, float ov1, int oi1) {
    if (better(ov0, oi0, v0, i0)) {
        if (better(v0, i0, ov1, oi1)) { v1 = v0; i1 = i0; }
        else                          { v1 = ov1; i1 = oi1; }
        v0 = ov0; i0 = oi0;
    } else {
        if (better(ov0, oi0, v1, i1)) { v1 = ov0; i1 = oi0; }
    }
}

// ---------------- 1. normalize ---------------------------------------------
// one warp per row of 128 floats
__global__ void normalize_k(const float* __restrict__ d0,
                            const float* __restrict__ d1) {
    int warp = (blockIdx.x * blockDim.x + threadIdx.x) >> 5;
    int lane = threadIdx.x & 31;
    const int total = BB * NN + BB * MM;
    if (warp >= total) return;

    const float* src;
    float* dst;
    if (warp < BB * NN) {
        src = d0 + (size_t)warp * DD;
        dst = g_d0n + (size_t)warp * DD;
    } else {
        int w = warp - BB * NN;
        src = d1 + (size_t)w * DD;
        dst = g_d1n + (size_t)w * DD;
    }

    float4 v = *(const float4*)(src + lane * 4);
    float s = v.x * v.x + v.y * v.y + v.z * v.z + v.w * v.w;
#pragma unroll
    for (int off = 16; off > 0; off >>= 1)
        s += __shfl_xor_sync(0xFFFFFFFFu, s, off);
    float inv = 1.0f / fmaxf(sqrtf(s), 1e-12f);
    v.x *= inv; v.y *= inv; v.z *= inv; v.w *= inv;
    *(float4*)(dst + lane * 4) = v;
}

// ---------------- 2. SGEMM: sim = d0n @ d1n^T -------------------------------
// tile 128x128, BK=16, 256 threads, TM=TN=8
#define BK 16
#define LDSM 132   // padded row length for smem tiles

__global__ __launch_bounds__(256)
void gemm_k(float* __restrict__ C) {
    __shared__ float As[BK * LDSM];
    __shared__ float Bs[BK * LDSM];

    const int b  = blockIdx.z;
    const int n0 = blockIdx.y * 128;
    const int m0 = blockIdx.x * 128;

    const float* __restrict__ Ab = g_d0n + ((size_t)b * NN + n0) * DD;
    const float* __restrict__ Bb = g_d1n + ((size_t)b * MM + m0) * DD;
    float* __restrict__ Cb = C + (size_t)b * NN * MM + (size_t)n0 * MM + m0;

    const int tid  = threadIdx.x;
    const int tcol = tid & 15;   // 0..15
    const int trow = tid >> 4;   // 0..15

    float acc[8][8];
#pragma unroll
    for (int i = 0; i < 8; i++)
#pragma unroll
        for (int j = 0; j < 8; j++) acc[i][j] = 0.0f;

    for (int k0 = 0; k0 < DD; k0 += BK) {
        // load 128x16 tiles of A and B, transposed into smem [k][row]
#pragma unroll
        for (int it = 0; it < 2; it++) {
            int f   = tid + it * 256;      // 0..511 float4 slots
            int row = f >> 2;              // 0..127
            int cv  = (f & 3) * 4;         // 0,4,8,12
            float4 av = *(const float4*)(Ab + (size_t)row * DD + k0 + cv);
            As[(cv + 0) * LDSM + row] = av.x;
            As[(cv + 1) * LDSM + row] = av.y;
            As[(cv + 2) * LDSM + row] = av.z;
            As[(cv + 3) * LDSM + row] = av.w;
            float4 bv = *(const float4*)(Bb + (size_t)row * DD + k0 + cv);
            Bs[(cv + 0) * LDSM + row] = bv.x;
            Bs[(cv + 1) * LDSM + row] = bv.y;
            Bs[(cv + 2) * LDSM + row] = bv.z;
            Bs[(cv + 3) * LDSM + row] = bv.w;
        }
        __syncthreads();

#pragma unroll
        for (int kk = 0; kk < BK; kk++) {
            float a[8], bb[8];
#pragma unroll
            for (int i = 0; i < 8; i++) a[i]  = As[kk * LDSM + trow * 8 + i];
#pragma unroll
            for (int j = 0; j < 8; j++) bb[j] = Bs[kk * LDSM + tcol * 8 + j];
#pragma unroll
            for (int i = 0; i < 8; i++)
#pragma unroll
                for (int j = 0; j < 8; j++)
                    acc[i][j] = fmaf(a[i], bb[j], acc[i][j]);
        }
        __syncthreads();
    }

    // write 8x8 per thread as float4s
#pragma unroll
    for (int i = 0; i < 8; i++) {
        size_t rowoff = (size_t)(trow * 8 + i) * MM + tcol * 8;
        float4 w0 = make_float4(acc[i][0], acc[i][1], acc[i][2], acc[i][3]);
        float4 w1 = make_float4(acc[i][4], acc[i][5], acc[i][6], acc[i][7]);
        *(float4*)(Cb + rowoff)     = w0;
        *(float4*)(Cb + rowoff + 4) = w1;
    }
}

// ---------------- 3. row top-2 (one warp per row of sim) --------------------
__global__ void row_top2_k(const float* __restrict__ sim) {
    int warp = (blockIdx.x * blockDim.x + threadIdx.x) >> 5;
    int lane = threadIdx.x & 31;
    if (warp >= BB * NN) return;

    const float* rowp = sim + (size_t)warp * MM;
    float v0 = -2.0f, v1 = -2.0f;
    int   i0 = -1,    i1 = -1;

#pragma unroll 4
    for (int it = 0; it < MM / 128; it++) {
        int c = it * 128 + lane * 4;
        float4 v = *(const float4*)(rowp + c);
        push2(v.x, c + 0, v0, i0, v1, i1);
        push2(v.y, c + 1, v0, i0, v1, i1);
        push2(v.z, c + 2, v0, i0, v1, i1);
        push2(v.w, c + 3, v0, i0, v1, i1);
    }
#pragma unroll
    for (int off = 16; off > 0; off >>= 1) {
        float ov0 = __shfl_xor_sync(0xFFFFFFFFu, v0, off);
        float ov1 = __shfl_xor_sync(0xFFFFFFFFu, v1, off);
        int   oi0 = __shfl_xor_sync(0xFFFFFFFFu, i0, off);
        int   oi1 = __shfl_xor_sync(0xFFFFFFFFu, i1, off);
        merge2(v0, i0, v1, i1, ov0, oi0, ov1, oi1);
    }
    if (lane == 0) {
        g_rv0[warp] = v0; g_rv1[warp] = v1;
        g_ri0[warp] = i0; g_ri1[warp] = i1;
    }
}

// ---------------- 4. col top-2 (one thread per column) ----------------------
// grid: BB * (MM/128) blocks of 128 threads; fully coalesced row sweeps
__global__ void col_top2_k(const float* __restrict__ sim) {
    int b   = blockIdx.x >> 5;                      // MM/128 = 32
    int col = (blockIdx.x & 31) * 128 + threadIdx.x;
    const float* base = sim + (size_t)b * NN * MM + col;

    float v0 = -2.0f, v1 = -2.0f;
    int   i0 = -1,    i1 = -1;

    for (int n = 0; n < NN; n += 4) {
        float a0 = base[(size_t)(n + 0) * MM];
        float a1 = base[(size_t)(n + 1) * MM];
        float a2 = base[(size_t)(n + 2) * MM];
        float a3 = base[(size_t)(n + 3) * MM];
        push2(a0, n + 0, v0, i0, v1, i1);
        push2(a1, n + 1, v0, i0, v1, i1);
        push2(a2, n + 2, v0, i0, v1, i1);
        push2(a3, n + 3, v0, i0, v1, i1);
    }
    int idx = b * MM + col;
    g_cv0[idx] = v0; g_cv1[idx] = v1;
    g_ci0[idx] = i0; g_ci1[idx] = i1;
}

// ---------------- 5a. ratio + distance test --------------------------------
__global__ void findnn_k() {
    int idx = blockIdx.x * blockDim.x + threadIdx.x;
    if (idx >= BB * NN) return;   // N == M, handles both sides

    // rows -> matches0 raw
    float d0 = 2.0f * (1.0f - g_rv0[idx]);
    float d1 = 2.0f * (1.0f - g_rv1[idx]);
    bool ok0 = (d0 <= 0.64f * d1) && (d0 <= 0.49f);
    g_m0raw[idx] = ok0 ? g_ri0[idx] : -1;

    // cols -> matches1 raw
    float c0 = 2.0f * (1.0f - g_cv0[idx]);
    float c1 = 2.0f * (1.0f - g_cv1[idx]);
    bool ok1 = (c0 <= 0.64f * c1) && (c0 <= 0.49f);
    g_m1raw[idx] = ok1 ? g_ci0[idx] : -1;
}

// ---------------- 5b. mutual check + output write ---------------------------
// out layout (fp32): matches0 [B*N] | matches1 [B*M] | mscores0 | mscores1 | sim
__global__ void mutual_k(float* __restrict__ out) {
    int idx = blockIdx.x * blockDim.x + threadIdx.x;
    if (idx >= BB * NN) return;
    int b = idx / NN;
    int n = idx - b * NN;   // also the column index for the matches1 side

    int m0 = g_m0raw[idx];
    bool good0 = (m0 > -1) && (g_m1raw[b * MM + m0] == n);
    out[idx] = good0 ? (float)m0 : -1.0f;
    out[2 * BB * NN + idx] = good0 ? 1.0f : 0.0f;

    int m1 = g_m1raw[idx];
    bool good1 = (m1 > -1) && (g_m0raw[b * NN + m1] == n);
    out[BB * NN + idx] = good1 ? (float)m1 : -1.0f;
    out[3 * BB * NN + idx] = good1 ? 1.0f : 0.0f;
}

// ---------------- launch -----------------------------------------------------
extern "C" void kernel_launch(void* const* d_in, const int* in_sizes, int n_in,
                              void* d_out, int out_size) {
    const float* desc0 = (const float*)d_in[0];
    const float* desc1 = (const float*)d_in[1];
    float* out = (float*)d_out;
    float* sim = out + 4 * BB * NN;   // sim region of the output

    // 1. normalize: (B*N + B*M) rows, 8 warps per 256-thread block
    {
        int warps = BB * NN + BB * MM;
        normalize_k<<<warps / 8, 256>>>(desc0, desc1);
    }

    // 2. GEMM -> sim
    {
        dim3 grid(MM / 128, NN / 128, BB);
        gemm_k<<<grid, 256>>>(sim);
    }

    // 3. row top-2: B*N warps
    {
        int warps = BB * NN;
        row_top2_k<<<warps / 8, 256>>>(sim);
    }

    // 4. col top-2
    {
        col_top2_k<<<BB * (MM / 128), 128>>>(sim);
    }

    // 5. thresholds + mutual check + writes
    {
        int t = BB * NN;
        findnn_k<<<(t + 255) / 256, 256>>>();
        mutual_k<<<(t + 255) / 256, 256>>>(out);
    }
}

// round 5
// speedup vs baseline: 1.2588x; 1.2588x over previous
#include <cuda_runtime.h>
#include <cuda_bf16.h>
#include <math.h>

#define BB 8
#define NN 4096
#define MM 4096
#define DD 128
#define NTILES 32          // 4096 / 128 tiles along each reduced dim

// ---------------- scratch (device globals: no allocation allowed) ----------
__device__ float g_d0n[BB * NN * DD];   // normalized descriptors0
__device__ float g_d1n[BB * MM * DD];   // normalized descriptors1

// per-tile partial top-2: [row/col global id][tile] -> (v0,v1) + (i0,i1)
__device__ float2 g_rp_v[BB * NN * NTILES];
__device__ int2   g_rp_i[BB * NN * NTILES];
__device__ float2 g_cp_v[BB * MM * NTILES];
__device__ int2   g_cp_i[BB * MM * NTILES];

__device__ int    g_m0raw[BB * NN];     // pre-mutual matches
__device__ int    g_m1raw[BB * MM];

// ---------------- helpers --------------------------------------------------
__device__ __forceinline__ void push2(float v, int i,
                                      float& v0, int& i0, float& v1, int& i1) {
    if (v > v0) { v1 = v0; i1 = i0; v0 = v; i0 = i; }
    else if (v > v1) { v1 = v; i1 = i; }
}

__device__ __forceinline__ bool better(float va, int ia, float vb, int ib) {
    return (va > vb) || (va == vb && ia < ib);
}

__device__ __forceinline__ void merge2(float& v0, int& i0, float& v1, int& i1,
                                       float ov0, int oi0, float ov1, int oi1) {
    if (better(ov0, oi0, v0, i0)) {
        if (better(v0, i0, ov1, oi1)) { v1 = v0; i1 = i0; }
        else                          { v1 = ov1; i1 = oi1; }
        v0 = ov0; i0 = oi0;
    } else {
        if (better(ov0, oi0, v1, i1)) { v1 = ov0; i1 = oi0; }
    }
}

// ---------------- 1. normalize ---------------------------------------------
__global__ void normalize_k(const float* __restrict__ d0,
                            const float* __restrict__ d1) {
    int warp = (blockIdx.x * blockDim.x + threadIdx.x) >> 5;
    int lane = threadIdx.x & 31;
    const int total = BB * NN + BB * MM;
    if (warp >= total) return;

    const float* src;
    float* dst;
    if (warp < BB * NN) {
        src = d0 + (size_t)warp * DD;
        dst = g_d0n + (size_t)warp * DD;
    } else {
        int w = warp - BB * NN;
        src = d1 + (size_t)w * DD;
        dst = g_d1n + (size_t)w * DD;
    }

    float4 v = *(const float4*)(src + lane * 4);
    float s = v.x * v.x + v.y * v.y + v.z * v.z + v.w * v.w;
#pragma unroll
    for (int off = 16; off > 0; off >>= 1)
        s += __shfl_xor_sync(0xFFFFFFFFu, s, off);
    float inv = 1.0f / fmaxf(sqrtf(s), 1e-12f);
    v.x *= inv; v.y *= inv; v.z *= inv; v.w *= inv;
    *(float4*)(dst + lane * 4) = v;
}

// ---------------- 2. SGEMM + fused top-2 partials ----------------------------
// tile 128x128, BK=16, 256 threads, TM=TN=8.
// Epilogue: row partial top-2 (shfl over tcol), col partial top-2 (smem over trow).
#define BK 16
#define LDSM 132   // padded row length for smem tiles

__global__ __launch_bounds__(256)
void gemm_k(float* __restrict__ C) {
    // union: A/B tiles during mainloop, col-reduction buffer in epilogue
    __shared__ float4 shbuf[16 * 128];            // 32 KB
    float* As = (float*)shbuf;                     // BK*LDSM floats
    float* Bs = As + BK * LDSM;                    // BK*LDSM floats (total 16896 B)

    const int b  = blockIdx.z;
    const int n0 = blockIdx.y * 128;
    const int m0 = blockIdx.x * 128;
    const int tileM = blockIdx.x;                  // column-tile index (0..31)
    const int tileN = blockIdx.y;                  // row-tile index    (0..31)

    const float* __restrict__ Ab = g_d0n + ((size_t)b * NN + n0) * DD;
    const float* __restrict__ Bb = g_d1n + ((size_t)b * MM + m0) * DD;
    float* __restrict__ Cb = C + (size_t)b * NN * MM + (size_t)n0 * MM + m0;

    const int tid  = threadIdx.x;
    const int tcol = tid & 15;   // 0..15
    const int trow = tid >> 4;   // 0..15

    float acc[8][8];
#pragma unroll
    for (int i = 0; i < 8; i++)
#pragma unroll
        for (int j = 0; j < 8; j++) acc[i][j] = 0.0f;

    for (int k0 = 0; k0 < DD; k0 += BK) {
#pragma unroll
        for (int it = 0; it < 2; it++) {
            int f   = tid + it * 256;
            int row = f >> 2;
            int cv  = (f & 3) * 4;
            float4 av = *(const float4*)(Ab + (size_t)row * DD + k0 + cv);
            As[(cv + 0) * LDSM + row] = av.x;
            As[(cv + 1) * LDSM + row] = av.y;
            As[(cv + 2) * LDSM + row] = av.z;
            As[(cv + 3) * LDSM + row] = av.w;
            float4 bv = *(const float4*)(Bb + (size_t)row * DD + k0 + cv);
            Bs[(cv + 0) * LDSM + row] = bv.x;
            Bs[(cv + 1) * LDSM + row] = bv.y;
            Bs[(cv + 2) * LDSM + row] = bv.z;
            Bs[(cv + 3) * LDSM + row] = bv.w;
        }
        __syncthreads();

#pragma unroll
        for (int kk = 0; kk < BK; kk++) {
            float a[8], bb[8];
#pragma unroll
            for (int i = 0; i < 8; i++) a[i]  = As[kk * LDSM + trow * 8 + i];
#pragma unroll
            for (int j = 0; j < 8; j++) bb[j] = Bs[kk * LDSM + tcol * 8 + j];
#pragma unroll
            for (int i = 0; i < 8; i++)
#pragma unroll
                for (int j = 0; j < 8; j++)
                    acc[i][j] = fmaf(a[i], bb[j], acc[i][j]);
        }
        __syncthreads();
    }

    // ---- write sim tile ----
#pragma unroll
    for (int i = 0; i < 8; i++) {
        size_t rowoff = (size_t)(trow * 8 + i) * MM + tcol * 8;
        *(float4*)(Cb + rowoff)     = make_float4(acc[i][0], acc[i][1], acc[i][2], acc[i][3]);
        *(float4*)(Cb + rowoff + 4) = make_float4(acc[i][4], acc[i][5], acc[i][6], acc[i][7]);
    }

    // ---- row partial top-2: reduce over 128 columns of this tile ----
    // threads sharing trow live in the same half-warp (lanes tcol / tcol+16)
#pragma unroll
    for (int i = 0; i < 8; i++) {
        float v0 = -2.0f, v1 = -2.0f;
        int   i0 = -1,    i1 = -1;
        int cbase = m0 + tcol * 8;
#pragma unroll
        for (int j = 0; j < 8; j++)
            push2(acc[i][j], cbase + j, v0, i0, v1, i1);
#pragma unroll
        for (int off = 8; off > 0; off >>= 1) {
            float ov0 = __shfl_xor_sync(0xFFFFFFFFu, v0, off);
            float ov1 = __shfl_xor_sync(0xFFFFFFFFu, v1, off);
            int   oi0 = __shfl_xor_sync(0xFFFFFFFFu, i0, off);
            int   oi1 = __shfl_xor_sync(0xFFFFFFFFu, i1, off);
            merge2(v0, i0, v1, i1, ov0, oi0, ov1, oi1);
        }
        if (tcol == 0) {
            size_t o = ((size_t)b * NN + n0 + trow * 8 + i) * NTILES + tileM;
            g_rp_v[o] = make_float2(v0, v1);
            g_rp_i[o] = make_int2(i0, i1);
        }
    }

    // ---- col partial top-2: reduce over 128 rows of this tile ----
    // per-thread top2 over its 8 rows, per column -> smem -> 128-thread final
    __syncthreads();   // everyone done with As/Bs reads above? (k-loop done; safe to reuse)
#pragma unroll
    for (int j = 0; j < 8; j++) {
        float v0 = -2.0f, v1 = -2.0f;
        int   i0 = -1,    i1 = -1;
        int rbase = n0 + trow * 8;
#pragma unroll
        for (int i = 0; i < 8; i++)
            push2(acc[i][j], rbase + i, v0, i0, v1, i1);
        shbuf[trow * 128 + tcol * 8 + j] =
            make_float4(v0, v1, __int_as_float(i0), __int_as_float(i1));
    }
    __syncthreads();

    if (tid < 128) {
        int col = tid;
        float v0 = -2.0f, v1 = -2.0f;
        int   i0 = -1,    i1 = -1;
#pragma unroll
        for (int t = 0; t < 16; t++) {
            float4 r = shbuf[t * 128 + col];
            merge2(v0, i0, v1, i1, r.x, __float_as_int(r.z),
                                   r.y, __float_as_int(r.w));
        }
        size_t o = ((size_t)b * MM + m0 + col) * NTILES + tileN;
        g_cp_v[o] = make_float2(v0, v1);
        g_cp_i[o] = make_int2(i0, i1);
    }
}

// ---------------- 3. merge partials + thresholds ------------------------------
// one warp per row (first BB*NN warps) or per column (next BB*MM warps);
// 32 lanes <-> exactly 32 tiles.
__global__ void merge_k() {
    int warp = (blockIdx.x * blockDim.x + threadIdx.x) >> 5;
    int lane = threadIdx.x & 31;
    const int nrows = BB * NN;
    if (warp >= nrows + BB * MM) return;

    float2 pv;
    int2   pi;
    if (warp < nrows) {
        pv = g_rp_v[(size_t)warp * NTILES + lane];
        pi = g_rp_i[(size_t)warp * NTILES + lane];
    } else {
        size_t w = warp - nrows;
        pv = g_cp_v[w * NTILES + lane];
        pi = g_cp_i[w * NTILES + lane];
    }
    float v0 = pv.x, v1 = pv.y;
    int   i0 = pi.x, i1 = pi.y;
#pragma unroll
    for (int off = 16; off > 0; off >>= 1) {
        float ov0 = __shfl_xor_sync(0xFFFFFFFFu, v0, off);
        float ov1 = __shfl_xor_sync(0xFFFFFFFFu, v1, off);
        int   oi0 = __shfl_xor_sync(0xFFFFFFFFu, i0, off);
        int   oi1 = __shfl_xor_sync(0xFFFFFFFFu, i1, off);
        merge2(v0, i0, v1, i1, ov0, oi0, ov1, oi1);
    }
    if (lane == 0) {
        float d0 = 2.0f * (1.0f - v0);
        float d1 = 2.0f * (1.0f - v1);
        bool ok = (d0 <= 0.64f * d1) && (d0 <= 0.49f);
        int m = ok ? i0 : -1;
        if (warp < nrows) g_m0raw[warp] = m;
        else              g_m1raw[warp - nrows] = m;
    }
}

// ---------------- 4. mutual check + output write -----------------------------
// out layout (fp32): matches0 [B*N] | matches1 [B*M] | mscores0 | mscores1 | sim
__global__ void mutual_k(float* __restrict__ out) {
    int idx = blockIdx.x * blockDim.x + threadIdx.x;
    if (idx >= BB * NN) return;
    int b = idx / NN;
    int n = idx - b * NN;

    int m0 = g_m0raw[idx];
    bool good0 = (m0 > -1) && (g_m1raw[b * MM + m0] == n);
    out[idx] = good0 ? (float)m0 : -1.0f;
    out[2 * BB * NN + idx] = good0 ? 1.0f : 0.0f;

    int m1 = g_m1raw[idx];
    bool good1 = (m1 > -1) && (g_m0raw[b * NN + m1] == n);
    out[BB * NN + idx] = good1 ? (float)m1 : -1.0f;
    out[3 * BB * NN + idx] = good1 ? 1.0f : 0.0f;
}

// ---------------- launch -----------------------------------------------------
extern "C" void kernel_launch(void* const* d_in, const int* in_sizes, int n_in,
                              void* d_out, int out_size) {
    const float* desc0 = (const float*)d_in[0];
    const float* desc1 = (const float*)d_in[1];
    float* out = (float*)d_out;
    float* sim = out + 4 * BB * NN;

    {
        int warps = BB * NN + BB * MM;
        normalize_k<<<warps / 8, 256>>>(desc0, desc1);
    }
    {
        dim3 grid(MM / 128, NN / 128, BB);
        gemm_k<<<grid, 256>>>(sim);
    }
    {
        int warps = 2 * BB * NN;            // rows + cols
        merge_k<<<warps / 8, 256>>>();
    }
    {
        int t = BB * NN;
        mutual_k<<<(t + 255) / 256, 256>>>(out);
    }
}